// round 5
// baseline (speedup 1.0000x reference)
#include <cuda_runtime.h>
#include <cstdint>

// Problem constants
#define BATCH 2
#define SEQ   2048
#define DMODEL 2048
#define NHEADS 16
#define HDIM  128
#define MROWS (BATCH*SEQ)          // 4096
#define PAIRS (BATCH*NHEADS)       // 32
#define EXP_SHIFT 20.0f

// ---------------- scratch (static __device__ globals; no allocation) --------
__device__ float g_Xt [MROWS*DMODEL];
__device__ float g_Wqt[DMODEL*DMODEL];
__device__ float g_Wkt[DMODEL*DMODEL];
__device__ float g_Wvt[DMODEL*DMODEL];
__device__ float g_Wot[DMODEL*DMODEL];
__device__ float g_Q  [MROWS*DMODEL];
__device__ float g_K  [MROWS*DMODEL];
__device__ float g_V  [MROWS*DMODEL];
__device__ float g_AO [MROWS*DMODEL];
__device__ float g_S  [(size_t)PAIRS*SEQ*SEQ];     // 512 MB exp-scores scratch

// ---------------- helpers ----------------------------------------------------
__device__ __forceinline__ float to_tf32(float v) {
    uint32_t r;
    asm("cvt.rna.tf32.f32 %0, %1;" : "=r"(r) : "f"(v));
    return __uint_as_float(r);
}

__device__ __forceinline__ void cp_async16(float* smem_dst, const float* gmem_src) {
    uint32_t s = (uint32_t)__cvta_generic_to_shared(smem_dst);
    asm volatile("cp.async.cg.shared.global [%0], [%1], 16;\n" :: "r"(s), "l"(gmem_src));
}
#define CP_COMMIT()  asm volatile("cp.async.commit_group;\n")
#define CP_WAIT(n)   asm volatile("cp.async.wait_group %0;\n" :: "n"(n))

// ---------------- elementwise fp32 -> tf32 (round-to-nearest) ---------------
__global__ void round_tf32_kernel(const float4* __restrict__ in,
                                  float4* __restrict__ out, int n4) {
    int i = blockIdx.x * blockDim.x + threadIdx.x;
    int stride = gridDim.x * blockDim.x;
    for (; i < n4; i += stride) {
        float4 v = in[i];
        v.x = to_tf32(v.x); v.y = to_tf32(v.y);
        v.z = to_tf32(v.z); v.w = to_tf32(v.w);
        out[i] = v;
    }
}

// ---------------- per-head RMSNorm (+ extra scale + tf32 round), in place ----
__global__ void __launch_bounds__(256)
rmsnorm_kernel(float* __restrict__ q, const float* __restrict__ gamma,
               float post_scale, int total_warps) {
    int gw   = (blockIdx.x * 256 + threadIdx.x) >> 5;
    int lane = threadIdx.x & 31;
    if (gw >= total_warps) return;
    float* p = q + (size_t)gw * HDIM;
    float v0 = p[lane], v1 = p[lane+32], v2 = p[lane+64], v3 = p[lane+96];
    float ss = v0*v0 + v1*v1 + v2*v2 + v3*v3;
    #pragma unroll
    for (int o = 16; o; o >>= 1) ss += __shfl_xor_sync(0xffffffffu, ss, o);
    float r = rsqrtf(ss * (1.0f/128.0f) + 1e-6f) * post_scale;
    p[lane]    = to_tf32(v0 * r * gamma[lane]);
    p[lane+32] = to_tf32(v1 * r * gamma[lane+32]);
    p[lane+64] = to_tf32(v2 * r * gamma[lane+64]);
    p[lane+96] = to_tf32(v3 * r * gamma[lane+96]);
}

// ---------------- generic TF32 tensor-core GEMM, 2-stage cp.async pipeline ---
// C[M,N] = A[M,K] * op(B). NN: B row-major [K,N]; NT: B row-major [N,K] (C=A*B^T)
// Block tile 128x128x32, 128 threads = 4 warps (2x2), warp tile 64x64.
// EPI: 0 = plain fp32 store; 1 = tf32-rounded store;
//      2 = tf32(exp(acc - EXP_SHIFT));
//      3 = tf32(acc / rowsum(A)), rowsum accumulated from A fragments in-loop
//          (valid since the K loop always spans the full row of A).
#define AS_STAGE 4608          // 128*36
#define BS_STAGE_NT 4608       // 128*36
#define BS_STAGE_NN 4352       // 32*136

template<bool NT, int EPI>
__global__ void __launch_bounds__(128)
gemm_tf32_kernel(const float* __restrict__ A, const float* __restrict__ B,
                 float* __restrict__ C,
                 int K, int lda, int ldb, int ldc,
                 int Z2,
                 long long sA1, long long sA2,
                 long long sB1, long long sB2,
                 long long sC1, long long sC2) {
    const int z  = blockIdx.z;
    int z1 = z / Z2, z2 = z % Z2;
    A += z1 * sA1 + z2 * sA2;
    B += z1 * sB1 + z2 * sB2;
    C += z1 * sC1 + z2 * sC2;

    extern __shared__ float smem[];
    float* As = smem;                 // [2][128][36]
    float* Bs = smem + 2 * AS_STAGE;  // NT: [2][128][36]; NN: [2][32][136]

    const int tid  = threadIdx.x;
    const int lane = tid & 31;
    const int warp = tid >> 5;
    const int wr = warp >> 1;      // 0..1 -> warp row (64)
    const int wc = warp & 1;       // 0..1 -> warp col (64)
    const int bm = blockIdx.y * 128;
    const int bn = blockIdx.x * 128;
    const int g  = lane >> 2;      // groupID 0..7
    const int tg = lane & 3;       // thread-in-group 0..3

    auto load_tile = [&](int kt, int s) {
        const int k0 = kt * 32;
        #pragma unroll
        for (int r = 0; r < 8; r++) {
            int idx = tid + r * 128;
            int row = idx >> 3;          // 8 float4 per row
            int c4  = idx & 7;
            cp_async16(&As[s * AS_STAGE + row * 36 + c4 * 4],
                       A + (long long)(bm + row) * lda + k0 + c4 * 4);
        }
        if (NT) {
            #pragma unroll
            for (int r = 0; r < 8; r++) {
                int idx = tid + r * 128;
                int row = idx >> 3;      // n-row, 8 float4 per row
                int c4  = idx & 7;
                cp_async16(&Bs[s * BS_STAGE_NT + row * 36 + c4 * 4],
                           B + (long long)(bn + row) * ldb + k0 + c4 * 4);
            }
        } else {
            #pragma unroll
            for (int r = 0; r < 8; r++) {
                int idx = tid + r * 128;
                int row = idx >> 5;      // k-row, 32 float4 per row
                int c4  = idx & 31;
                cp_async16(&Bs[s * BS_STAGE_NN + row * 136 + c4 * 4],
                           B + (long long)(k0 + row) * ldb + bn + c4 * 4);
            }
        }
    };

    float acc[4][8][4];
    #pragma unroll
    for (int i = 0; i < 4; i++)
        #pragma unroll
        for (int j = 0; j < 8; j++)
            #pragma unroll
            for (int c = 0; c < 4; c++) acc[i][j][c] = 0.0f;

    // EPI==3: per-thread partial row sums of A, accumulated from fragments.
    // Only wc==0 warps contribute (wc==1 loads identical A fragments).
    float rs0[4], rs1[4];
    #pragma unroll
    for (int i = 0; i < 4; i++) { rs0[i] = 0.0f; rs1[i] = 0.0f; }

    const int KT = K >> 5;             // k-tiles of 32
    load_tile(0, 0);
    CP_COMMIT();

    for (int kt = 0; kt < KT; kt++) {
        const int s = kt & 1;
        if (kt + 1 < KT) {
            load_tile(kt + 1, s ^ 1);
            CP_COMMIT();
            CP_WAIT(1);                // stage s resident
        } else {
            CP_WAIT(0);
        }
        __syncthreads();

        const float* Asb = &As[s * AS_STAGE];
        const float* Bsb = NT ? &Bs[s * BS_STAGE_NT] : &Bs[s * BS_STAGE_NN];

        #pragma unroll
        for (int ks = 0; ks < 4; ks++) {
            const int kk = ks * 8;
            uint32_t af[4][4];
            #pragma unroll
            for (int i = 0; i < 4; i++) {
                int r0 = wr * 64 + i * 16 + g;
                af[i][0] = __float_as_uint(Asb[(r0    ) * 36 + kk + tg    ]);
                af[i][1] = __float_as_uint(Asb[(r0 + 8) * 36 + kk + tg    ]);
                af[i][2] = __float_as_uint(Asb[(r0    ) * 36 + kk + tg + 4]);
                af[i][3] = __float_as_uint(Asb[(r0 + 8) * 36 + kk + tg + 4]);
            }
            if (EPI == 3 && wc == 0) {
                #pragma unroll
                for (int i = 0; i < 4; i++) {
                    rs0[i] += __uint_as_float(af[i][0]) + __uint_as_float(af[i][2]);
                    rs1[i] += __uint_as_float(af[i][1]) + __uint_as_float(af[i][3]);
                }
            }
            uint32_t bf[8][2];
            #pragma unroll
            for (int j = 0; j < 8; j++) {
                int n = wc * 64 + j * 8 + g;
                if (NT) {
                    bf[j][0] = __float_as_uint(Bsb[n * 36 + kk + tg    ]);
                    bf[j][1] = __float_as_uint(Bsb[n * 36 + kk + tg + 4]);
                } else {
                    bf[j][0] = __float_as_uint(Bsb[(kk + tg    ) * 136 + n]);
                    bf[j][1] = __float_as_uint(Bsb[(kk + tg + 4) * 136 + n]);
                }
            }
            #pragma unroll
            for (int i = 0; i < 4; i++)
                #pragma unroll
                for (int j = 0; j < 8; j++) {
                    asm volatile(
                        "mma.sync.aligned.m16n8k8.row.col.f32.tf32.tf32.f32 "
                        "{%0,%1,%2,%3}, {%4,%5,%6,%7}, {%8,%9}, {%0,%1,%2,%3};\n"
                        : "+f"(acc[i][j][0]), "+f"(acc[i][j][1]),
                          "+f"(acc[i][j][2]), "+f"(acc[i][j][3])
                        : "r"(af[i][0]), "r"(af[i][1]), "r"(af[i][2]), "r"(af[i][3]),
                          "r"(bf[j][0]), "r"(bf[j][1]));
                }
        }
        __syncthreads();     // stage s fully consumed before it is refilled
    }

    // EPI==3: reduce partials across the 4-lane k-groups, publish row sums.
    float* rowsum = smem;    // reuse As stage 0 (mainloop finished, post-sync)
    if (EPI == 3) {
        if (wc == 0) {
            #pragma unroll
            for (int i = 0; i < 4; i++) {
                rs0[i] += __shfl_xor_sync(0xffffffffu, rs0[i], 1);
                rs0[i] += __shfl_xor_sync(0xffffffffu, rs0[i], 2);
                rs1[i] += __shfl_xor_sync(0xffffffffu, rs1[i], 1);
                rs1[i] += __shfl_xor_sync(0xffffffffu, rs1[i], 2);
                if (tg == 0) {
                    rowsum[wr * 64 + i * 16 + g]     = rs0[i];
                    rowsum[wr * 64 + i * 16 + g + 8] = rs1[i];
                }
            }
        }
        __syncthreads();
    }

    // -- epilogue: m16n8 C fragment layout, with fused postprocessing
    #pragma unroll
    for (int i = 0; i < 4; i++) {
        int rl = wr * 64 + i * 16 + g;          // local row in [0,128)
        long long r0 = bm + rl;
        float invA = 1.0f, invB = 1.0f;
        if (EPI == 3) {
            invA = 1.0f / rowsum[rl];
            invB = 1.0f / rowsum[rl + 8];
        }
        #pragma unroll
        for (int j = 0; j < 8; j++) {
            int c0 = bn + wc * 64 + j * 8 + tg * 2;
            float o0 = acc[i][j][0], o1 = acc[i][j][1];
            float o2 = acc[i][j][2], o3 = acc[i][j][3];
            if (EPI == 1) {
                o0 = to_tf32(o0); o1 = to_tf32(o1);
                o2 = to_tf32(o2); o3 = to_tf32(o3);
            } else if (EPI == 2) {
                o0 = to_tf32(__expf(o0 - EXP_SHIFT));
                o1 = to_tf32(__expf(o1 - EXP_SHIFT));
                o2 = to_tf32(__expf(o2 - EXP_SHIFT));
                o3 = to_tf32(__expf(o3 - EXP_SHIFT));
            } else if (EPI == 3) {
                o0 = to_tf32(o0 * invA); o1 = to_tf32(o1 * invA);
                o2 = to_tf32(o2 * invB); o3 = to_tf32(o3 * invB);
            }
            C[r0 * ldc + c0]           = o0;
            C[r0 * ldc + c0 + 1]       = o1;
            C[(r0 + 8) * ldc + c0]     = o2;
            C[(r0 + 8) * ldc + c0 + 1] = o3;
        }
    }
}

#define SMEM_NT ((2*AS_STAGE + 2*BS_STAGE_NT) * 4)   // 73728 B
#define SMEM_NN ((2*AS_STAGE + 2*BS_STAGE_NN) * 4)   // 71680 B

// ---------------- launcher ----------------------------------------------------
extern "C" void kernel_launch(void* const* d_in, const int* in_sizes, int n_in,
                              void* d_out, int out_size) {
    (void)in_sizes; (void)n_in; (void)out_size;
    const float* x  = (const float*)d_in[0];
    const float* Wq = (const float*)d_in[1];
    const float* Wk = (const float*)d_in[2];
    const float* Wv = (const float*)d_in[3];
    const float* Wo = (const float*)d_in[4];
    const float* qg = (const float*)d_in[5];
    const float* kg = (const float*)d_in[6];
    float* out = (float*)d_out;

    float *Xt, *Wqt, *Wkt, *Wvt, *Wot, *Q, *Kb, *V, *AO, *S;
    cudaGetSymbolAddress((void**)&Xt,  g_Xt);
    cudaGetSymbolAddress((void**)&Wqt, g_Wqt);
    cudaGetSymbolAddress((void**)&Wkt, g_Wkt);
    cudaGetSymbolAddress((void**)&Wvt, g_Wvt);
    cudaGetSymbolAddress((void**)&Wot, g_Wot);
    cudaGetSymbolAddress((void**)&Q,   g_Q);
    cudaGetSymbolAddress((void**)&Kb,  g_K);
    cudaGetSymbolAddress((void**)&V,   g_V);
    cudaGetSymbolAddress((void**)&AO,  g_AO);
    cudaGetSymbolAddress((void**)&S,   g_S);

    cudaFuncSetAttribute(gemm_tf32_kernel<false,0>,
                         cudaFuncAttributeMaxDynamicSharedMemorySize, SMEM_NN);
    cudaFuncSetAttribute(gemm_tf32_kernel<false,1>,
                         cudaFuncAttributeMaxDynamicSharedMemorySize, SMEM_NN);
    cudaFuncSetAttribute(gemm_tf32_kernel<false,3>,
                         cudaFuncAttributeMaxDynamicSharedMemorySize, SMEM_NN);
    cudaFuncSetAttribute(gemm_tf32_kernel<true,2>,
                         cudaFuncAttributeMaxDynamicSharedMemorySize, SMEM_NT);

    const int M = MROWS, D = DMODEL;
    const long long PS = (long long)SEQ * SEQ;   // per-(b,h) scores stride

    // 1) round all GEMM inputs to tf32 (rna) for accuracy
    round_tf32_kernel<<<2048, 256>>>((const float4*)x,  (float4*)Xt,  M*D/4);
    round_tf32_kernel<<<2048, 256>>>((const float4*)Wq, (float4*)Wqt, D*D/4);
    round_tf32_kernel<<<2048, 256>>>((const float4*)Wk, (float4*)Wkt, D*D/4);
    round_tf32_kernel<<<2048, 256>>>((const float4*)Wv, (float4*)Wvt, D*D/4);
    round_tf32_kernel<<<2048, 256>>>((const float4*)Wo, (float4*)Wot, D*D/4);

    // 2) QKV projections: [4096,2048] x [2048,2048]; V output tf32-rounded
    dim3 gProj(D/128, M/128, 1);
    gemm_tf32_kernel<false,0><<<gProj, 128, SMEM_NN>>>(Xt, Wqt, Q,  D, D, D, D, 1, 0,0,0,0,0,0);
    gemm_tf32_kernel<false,0><<<gProj, 128, SMEM_NN>>>(Xt, Wkt, Kb, D, D, D, D, 1, 0,0,0,0,0,0);
    gemm_tf32_kernel<false,1><<<gProj, 128, SMEM_NN>>>(Xt, Wvt, V,  D, D, D, D, 1, 0,0,0,0,0,0);

    // 3) per-head RMSNorm on Q (folds in 1/sqrt(HDIM)) and K, tf32-rounded
    const float att_scale = 0.08838834764831845f;   // 1/sqrt(128)
    rmsnorm_kernel<<<M*NHEADS/8, 256>>>(Q,  qg, att_scale, M*NHEADS);
    rmsnorm_kernel<<<M*NHEADS/8, 256>>>(Kb, kg, 1.0f,      M*NHEADS);

    // 4) exp-scores: per (b,h)  E_bh = exp(Q_bh K_bh^T - SHIFT), tf32-rounded
    dim3 gScores(SEQ/128, SEQ/128, PAIRS);
    gemm_tf32_kernel<true,2><<<gScores, 128, SMEM_NT>>>(
        Q, Kb, S, HDIM, D, D, SEQ,
        NHEADS,
        (long long)SEQ*D, HDIM,
        (long long)SEQ*D, HDIM,
        NHEADS*PS,        PS);

    // 5) PV with fused in-loop rowsum + normalization:
    //    AO_bh = (E_bh V_bh) / rowsum(E_bh)
    dim3 gPV(HDIM/128, SEQ/128, PAIRS);
    gemm_tf32_kernel<false,3><<<gPV, 128, SMEM_NN>>>(
        S, V, AO, SEQ, SEQ, D, D,
        NHEADS,
        NHEADS*PS,        PS,
        (long long)SEQ*D, HDIM,
        (long long)SEQ*D, HDIM);

    // 6) output projection: out = AO x Wo
    gemm_tf32_kernel<false,0><<<gProj, 128, SMEM_NN>>>(AO, Wot, out, D, D, D, D, 1, 0,0,0,0,0,0);
}

// round 6
// speedup vs baseline: 1.0279x; 1.0279x over previous
#include <cuda_runtime.h>
#include <cstdint>

// Problem constants
#define BATCH 2
#define SEQ   2048
#define DMODEL 2048
#define NHEADS 16
#define HDIM  128
#define MROWS (BATCH*SEQ)          // 4096
#define PAIRS (BATCH*NHEADS)       // 32
#define EXP_SHIFT 20.0f

// ---------------- scratch (static __device__ globals; no allocation) --------
__device__ float g_Xt [MROWS*DMODEL];
__device__ float g_Wqt[DMODEL*DMODEL];
__device__ float g_Wkt[DMODEL*DMODEL];
__device__ float g_Wvt[DMODEL*DMODEL];
__device__ float g_Wot[DMODEL*DMODEL];
__device__ float g_Q  [MROWS*DMODEL];
__device__ float g_K  [MROWS*DMODEL];
__device__ float g_V  [MROWS*DMODEL];
__device__ float g_AO [MROWS*DMODEL];

// ---------------- helpers ----------------------------------------------------
__device__ __forceinline__ float to_tf32(float v) {
    uint32_t r;
    asm("cvt.rna.tf32.f32 %0, %1;" : "=r"(r) : "f"(v));
    return __uint_as_float(r);
}

__device__ __forceinline__ void cp_async16(float* smem_dst, const float* gmem_src) {
    uint32_t s = (uint32_t)__cvta_generic_to_shared(smem_dst);
    asm volatile("cp.async.cg.shared.global [%0], [%1], 16;\n" :: "r"(s), "l"(gmem_src));
}
#define CP_COMMIT()  asm volatile("cp.async.commit_group;\n")
#define CP_WAIT(n)   asm volatile("cp.async.wait_group %0;\n" :: "n"(n))

#define MMA_TF32(acc, a0,a1,a2,a3, b0,b1) \
    asm volatile("mma.sync.aligned.m16n8k8.row.col.f32.tf32.tf32.f32 " \
        "{%0,%1,%2,%3}, {%4,%5,%6,%7}, {%8,%9}, {%0,%1,%2,%3};\n" \
        : "+f"(acc[0]), "+f"(acc[1]), "+f"(acc[2]), "+f"(acc[3]) \
        : "r"(a0), "r"(a1), "r"(a2), "r"(a3), "r"(b0), "r"(b1))

// ---------------- elementwise fp32 -> tf32 (round-to-nearest) ---------------
__global__ void round_tf32_kernel(const float4* __restrict__ in,
                                  float4* __restrict__ out, int n4) {
    int i = blockIdx.x * blockDim.x + threadIdx.x;
    int stride = gridDim.x * blockDim.x;
    for (; i < n4; i += stride) {
        float4 v = in[i];
        v.x = to_tf32(v.x); v.y = to_tf32(v.y);
        v.z = to_tf32(v.z); v.w = to_tf32(v.w);
        out[i] = v;
    }
}

// ---------------- per-head RMSNorm (+ extra scale + tf32 round), in place ----
__global__ void __launch_bounds__(256)
rmsnorm_kernel(float* __restrict__ q, const float* __restrict__ gamma,
               float post_scale, int total_warps) {
    int gw   = (blockIdx.x * 256 + threadIdx.x) >> 5;
    int lane = threadIdx.x & 31;
    if (gw >= total_warps) return;
    float* p = q + (size_t)gw * HDIM;
    float v0 = p[lane], v1 = p[lane+32], v2 = p[lane+64], v3 = p[lane+96];
    float ss = v0*v0 + v1*v1 + v2*v2 + v3*v3;
    #pragma unroll
    for (int o = 16; o; o >>= 1) ss += __shfl_xor_sync(0xffffffffu, ss, o);
    float r = rsqrtf(ss * (1.0f/128.0f) + 1e-6f) * post_scale;
    p[lane]    = to_tf32(v0 * r * gamma[lane]);
    p[lane+32] = to_tf32(v1 * r * gamma[lane+32]);
    p[lane+64] = to_tf32(v2 * r * gamma[lane+64]);
    p[lane+96] = to_tf32(v3 * r * gamma[lane+96]);
}

// ---------------- TF32 NN GEMM (projections), 2-stage cp.async ---------------
// C[M,N] = A[M,K] * B[K,N], all row-major. 128x128x32 tile, 256 thr, 8 warps
// (2x4), warp tile 64x32.  EPI: 0 = fp32 store; 1 = tf32-rounded store.
#define AS_STAGE 4608          // 128*36
#define BS_STAGE 4352          // 32*136
#define SMEM_GEMM ((2*AS_STAGE + 2*BS_STAGE) * 4)   // 71680 B

template<int EPI>
__global__ void __launch_bounds__(256)
gemm_tf32_kernel(const float* __restrict__ A, const float* __restrict__ B,
                 float* __restrict__ C, int K, int lda, int ldb, int ldc) {
    extern __shared__ float smem[];
    float* As = smem;                 // [2][128][36]
    float* Bs = smem + 2 * AS_STAGE;  // [2][32][136]

    const int tid  = threadIdx.x;
    const int lane = tid & 31;
    const int warp = tid >> 5;
    const int wr = warp >> 2;      // 0..1 -> warp row (64)
    const int wc = warp & 3;       // 0..3 -> warp col (32)
    const int bm = blockIdx.y * 128;
    const int bn = blockIdx.x * 128;
    const int g  = lane >> 2;
    const int tg = lane & 3;

    auto load_tile = [&](int kt, int s) {
        const int k0 = kt * 32;
        #pragma unroll
        for (int r = 0; r < 4; r++) {
            int idx = tid + r * 256;
            int row = idx >> 3;          // 8 float4 per row
            int c4  = idx & 7;
            cp_async16(&As[s * AS_STAGE + row * 36 + c4 * 4],
                       A + (long long)(bm + row) * lda + k0 + c4 * 4);
        }
        #pragma unroll
        for (int r = 0; r < 4; r++) {
            int idx = tid + r * 256;
            int row = idx >> 5;          // k-row, 32 float4 per row
            int c4  = idx & 31;
            cp_async16(&Bs[s * BS_STAGE + row * 136 + c4 * 4],
                       B + (long long)(k0 + row) * ldb + bn + c4 * 4);
        }
    };

    float acc[4][4][4];
    #pragma unroll
    for (int i = 0; i < 4; i++)
        #pragma unroll
        for (int j = 0; j < 4; j++)
            #pragma unroll
            for (int c = 0; c < 4; c++) acc[i][j][c] = 0.0f;

    const int KT = K >> 5;
    load_tile(0, 0);
    CP_COMMIT();

    for (int kt = 0; kt < KT; kt++) {
        const int s = kt & 1;
        if (kt + 1 < KT) {
            load_tile(kt + 1, s ^ 1);
            CP_COMMIT();
            CP_WAIT(1);
        } else {
            CP_WAIT(0);
        }
        __syncthreads();

        const float* Asb = &As[s * AS_STAGE];
        const float* Bsb = &Bs[s * BS_STAGE];

        #pragma unroll
        for (int ks = 0; ks < 4; ks++) {
            const int kk = ks * 8;
            uint32_t af[4][4];
            #pragma unroll
            for (int i = 0; i < 4; i++) {
                int r0 = wr * 64 + i * 16 + g;
                af[i][0] = __float_as_uint(Asb[(r0    ) * 36 + kk + tg    ]);
                af[i][1] = __float_as_uint(Asb[(r0 + 8) * 36 + kk + tg    ]);
                af[i][2] = __float_as_uint(Asb[(r0    ) * 36 + kk + tg + 4]);
                af[i][3] = __float_as_uint(Asb[(r0 + 8) * 36 + kk + tg + 4]);
            }
            uint32_t bf[4][2];
            #pragma unroll
            for (int j = 0; j < 4; j++) {
                int n = wc * 32 + j * 8 + g;
                bf[j][0] = __float_as_uint(Bsb[(kk + tg    ) * 136 + n]);
                bf[j][1] = __float_as_uint(Bsb[(kk + tg + 4) * 136 + n]);
            }
            #pragma unroll
            for (int i = 0; i < 4; i++)
                #pragma unroll
                for (int j = 0; j < 4; j++)
                    MMA_TF32(acc[i][j], af[i][0], af[i][1], af[i][2], af[i][3],
                             bf[j][0], bf[j][1]);
        }
        __syncthreads();
    }

    #pragma unroll
    for (int i = 0; i < 4; i++) {
        long long r0 = bm + wr * 64 + i * 16 + g;
        #pragma unroll
        for (int j = 0; j < 4; j++) {
            int c0 = bn + wc * 32 + j * 8 + tg * 2;
            float o0 = acc[i][j][0], o1 = acc[i][j][1];
            float o2 = acc[i][j][2], o3 = acc[i][j][3];
            if (EPI == 1) {
                o0 = to_tf32(o0); o1 = to_tf32(o1);
                o2 = to_tf32(o2); o3 = to_tf32(o3);
            }
            C[r0 * ldc + c0]           = o0;
            C[r0 * ldc + c0 + 1]       = o1;
            C[(r0 + 8) * ldc + c0]     = o2;
            C[(r0 + 8) * ldc + c0 + 1] = o3;
        }
    }
}

// ---------------- fused attention ---------------------------------------------
// One CTA = one 128-row q-tile of one (b,h). Streams keys in 64-row chunks:
//   S = Qs @ Ks^T  ->  P = tf32(exp(S - SHIFT))  ->  O += P @ Vs
// Row sums of P accumulate in registers across chunks (fixed shift => no
// rescaling). Final: AO = tf32(O / rowsum).
// smem: Qs[128][132] | Ks[64][132] | Vs[64][132] | Ps[128][68]
#define QSTR 132
#define PSTR 68
#define ATTN_SMEM ((128*QSTR + 64*QSTR + 64*QSTR + 128*PSTR) * 4)  // 169984 B

__global__ void __launch_bounds__(256)
attn_kernel(const float* __restrict__ Qg, const float* __restrict__ Kg,
            const float* __restrict__ Vg, float* __restrict__ AO) {
    const int qx = blockIdx.x;              // 0..15 q-tile
    const int b  = blockIdx.y >> 4;
    const int h  = blockIdx.y & 15;
    const long long baseQ = ((long long)b * SEQ + qx * 128) * DMODEL + h * HDIM;
    const long long baseK = ((long long)b * SEQ) * DMODEL + h * HDIM;

    extern __shared__ float smem[];
    float* Qs = smem;
    float* Ks = Qs + 128 * QSTR;
    float* Vs = Ks + 64 * QSTR;
    float* Ps = Vs + 64 * QSTR;

    const int tid  = threadIdx.x;
    const int lane = tid & 31;
    const int warp = tid >> 5;
    const int wr   = warp >> 1;             // 0..3 (32-row blocks)
    const int wc   = warp & 1;              // 0..1
    const int g    = lane >> 2;
    const int tg   = lane & 3;

    // prologue: Q tile (group 0), K0 (group 1), V0 (group 2)
    #pragma unroll
    for (int r = 0; r < 16; r++) {
        int idx = tid + r * 256, row = idx >> 5, c4 = idx & 31;
        cp_async16(&Qs[row * QSTR + c4 * 4],
                   Qg + baseQ + (long long)row * DMODEL + c4 * 4);
    }
    CP_COMMIT();
    auto load_chunk = [&](const float* src, float* dst, int kt) {
        #pragma unroll
        for (int r = 0; r < 8; r++) {
            int idx = tid + r * 256, row = idx >> 5, c4 = idx & 31;
            cp_async16(&dst[row * QSTR + c4 * 4],
                       src + baseK + (long long)(kt * 64 + row) * DMODEL + c4 * 4);
        }
        CP_COMMIT();
    };
    load_chunk(Kg, Ks, 0);
    load_chunk(Vg, Vs, 0);

    float acc_o[2][8][4];
    #pragma unroll
    for (int i = 0; i < 2; i++)
        #pragma unroll
        for (int j = 0; j < 8; j++)
            #pragma unroll
            for (int c = 0; c < 4; c++) acc_o[i][j][c] = 0.0f;
    float rs[2][2] = {{0.0f, 0.0f}, {0.0f, 0.0f}};

    for (int kt = 0; kt < 32; kt++) {
        CP_WAIT(1);                 // Q (first iter) + K(kt) resident
        __syncthreads();

        // ---- S = Qs @ Ks^T  (128x64, k = 128)
        float acc_s[2][4][4];
        #pragma unroll
        for (int i = 0; i < 2; i++)
            #pragma unroll
            for (int j = 0; j < 4; j++)
                #pragma unroll
                for (int c = 0; c < 4; c++) acc_s[i][j][c] = 0.0f;

        #pragma unroll
        for (int ks = 0; ks < 16; ks++) {
            const int kk = ks * 8;
            uint32_t af[2][4];
            #pragma unroll
            for (int i = 0; i < 2; i++) {
                int r0 = wr * 32 + i * 16 + g;
                af[i][0] = __float_as_uint(Qs[(r0    ) * QSTR + kk + tg    ]);
                af[i][1] = __float_as_uint(Qs[(r0 + 8) * QSTR + kk + tg    ]);
                af[i][2] = __float_as_uint(Qs[(r0    ) * QSTR + kk + tg + 4]);
                af[i][3] = __float_as_uint(Qs[(r0 + 8) * QSTR + kk + tg + 4]);
            }
            uint32_t bf[4][2];
            #pragma unroll
            for (int j = 0; j < 4; j++) {
                int n = wc * 32 + j * 8 + g;
                bf[j][0] = __float_as_uint(Ks[n * QSTR + kk + tg    ]);
                bf[j][1] = __float_as_uint(Ks[n * QSTR + kk + tg + 4]);
            }
            #pragma unroll
            for (int i = 0; i < 2; i++)
                #pragma unroll
                for (int j = 0; j < 4; j++)
                    MMA_TF32(acc_s[i][j], af[i][0], af[i][1], af[i][2], af[i][3],
                             bf[j][0], bf[j][1]);
        }

        // ---- P = tf32(exp(S - SHIFT)), accumulate row sums, store to smem
        #pragma unroll
        for (int i = 0; i < 2; i++) {
            int r0 = wr * 32 + i * 16 + g;
            #pragma unroll
            for (int j = 0; j < 4; j++) {
                int c0 = wc * 32 + j * 8 + tg * 2;
                float e0 = to_tf32(__expf(acc_s[i][j][0] - EXP_SHIFT));
                float e1 = to_tf32(__expf(acc_s[i][j][1] - EXP_SHIFT));
                float e2 = to_tf32(__expf(acc_s[i][j][2] - EXP_SHIFT));
                float e3 = to_tf32(__expf(acc_s[i][j][3] - EXP_SHIFT));
                rs[i][0] += e0 + e1;
                rs[i][1] += e2 + e3;
                *(float2*)&Ps[(r0    ) * PSTR + c0] = make_float2(e0, e1);
                *(float2*)&Ps[(r0 + 8) * PSTR + c0] = make_float2(e2, e3);
            }
        }
        __syncthreads();            // Ps visible; Ks fully consumed

        if (kt + 1 < 32) load_chunk(Kg, Ks, kt + 1);   // hides under PV GEMM
        if (kt + 1 < 32) { CP_WAIT(1); } else { CP_WAIT(0); }  // V(kt) resident
        __syncthreads();

        // ---- O += Ps @ Vs  (128x128, k = 64)
        #pragma unroll
        for (int ks = 0; ks < 8; ks++) {
            const int kk = ks * 8;
            uint32_t af[2][4];
            #pragma unroll
            for (int i = 0; i < 2; i++) {
                int r0 = wr * 32 + i * 16 + g;
                af[i][0] = __float_as_uint(Ps[(r0    ) * PSTR + kk + tg    ]);
                af[i][1] = __float_as_uint(Ps[(r0 + 8) * PSTR + kk + tg    ]);
                af[i][2] = __float_as_uint(Ps[(r0    ) * PSTR + kk + tg + 4]);
                af[i][3] = __float_as_uint(Ps[(r0 + 8) * PSTR + kk + tg + 4]);
            }
            uint32_t bf[8][2];
            #pragma unroll
            for (int j = 0; j < 8; j++) {
                int n = wc * 64 + j * 8 + g;
                bf[j][0] = __float_as_uint(Vs[(kk + tg    ) * QSTR + n]);
                bf[j][1] = __float_as_uint(Vs[(kk + tg + 4) * QSTR + n]);
            }
            #pragma unroll
            for (int i = 0; i < 2; i++)
                #pragma unroll
                for (int j = 0; j < 8; j++)
                    MMA_TF32(acc_o[i][j], af[i][0], af[i][1], af[i][2], af[i][3],
                             bf[j][0], bf[j][1]);
        }
        __syncthreads();            // Vs + Ps fully consumed

        if (kt + 1 < 32) load_chunk(Vg, Vs, kt + 1);   // hides under next S GEMM
    }

    // ---- final row sums: reduce over the 4-lane k-groups, then across wc
    #pragma unroll
    for (int i = 0; i < 2; i++) {
        rs[i][0] += __shfl_xor_sync(0xffffffffu, rs[i][0], 1);
        rs[i][0] += __shfl_xor_sync(0xffffffffu, rs[i][0], 2);
        rs[i][1] += __shfl_xor_sync(0xffffffffu, rs[i][1], 1);
        rs[i][1] += __shfl_xor_sync(0xffffffffu, rs[i][1], 2);
    }
    float* rsbuf = Ps;              // [2][128], Ps no longer needed
    if (tg == 0) {
        #pragma unroll
        for (int i = 0; i < 2; i++) {
            rsbuf[wc * 128 + wr * 32 + i * 16 + g]     = rs[i][0];
            rsbuf[wc * 128 + wr * 32 + i * 16 + g + 8] = rs[i][1];
        }
    }
    __syncthreads();

    // ---- epilogue: AO = tf32(O / rowsum)
    #pragma unroll
    for (int i = 0; i < 2; i++) {
        int rl = wr * 32 + i * 16 + g;
        float inv0 = 1.0f / (rsbuf[rl]     + rsbuf[128 + rl]);
        float inv1 = 1.0f / (rsbuf[rl + 8] + rsbuf[128 + rl + 8]);
        long long gr0 = baseQ + (long long)rl * DMODEL;
        #pragma unroll
        for (int j = 0; j < 8; j++) {
            int c0 = wc * 64 + j * 8 + tg * 2;
            AO[gr0 + c0]                 = to_tf32(acc_o[i][j][0] * inv0);
            AO[gr0 + c0 + 1]             = to_tf32(acc_o[i][j][1] * inv0);
            AO[gr0 + 8 * DMODEL + c0]     = to_tf32(acc_o[i][j][2] * inv1);
            AO[gr0 + 8 * DMODEL + c0 + 1] = to_tf32(acc_o[i][j][3] * inv1);
        }
    }
}

// ---------------- launcher ----------------------------------------------------
extern "C" void kernel_launch(void* const* d_in, const int* in_sizes, int n_in,
                              void* d_out, int out_size) {
    (void)in_sizes; (void)n_in; (void)out_size;
    const float* x  = (const float*)d_in[0];
    const float* Wq = (const float*)d_in[1];
    const float* Wk = (const float*)d_in[2];
    const float* Wv = (const float*)d_in[3];
    const float* Wo = (const float*)d_in[4];
    const float* qg = (const float*)d_in[5];
    const float* kg = (const float*)d_in[6];
    float* out = (float*)d_out;

    float *Xt, *Wqt, *Wkt, *Wvt, *Wot, *Q, *Kb, *V, *AO;
    cudaGetSymbolAddress((void**)&Xt,  g_Xt);
    cudaGetSymbolAddress((void**)&Wqt, g_Wqt);
    cudaGetSymbolAddress((void**)&Wkt, g_Wkt);
    cudaGetSymbolAddress((void**)&Wvt, g_Wvt);
    cudaGetSymbolAddress((void**)&Wot, g_Wot);
    cudaGetSymbolAddress((void**)&Q,   g_Q);
    cudaGetSymbolAddress((void**)&Kb,  g_K);
    cudaGetSymbolAddress((void**)&V,   g_V);
    cudaGetSymbolAddress((void**)&AO,  g_AO);

    cudaFuncSetAttribute(gemm_tf32_kernel<0>,
                         cudaFuncAttributeMaxDynamicSharedMemorySize, SMEM_GEMM);
    cudaFuncSetAttribute(gemm_tf32_kernel<1>,
                         cudaFuncAttributeMaxDynamicSharedMemorySize, SMEM_GEMM);
    cudaFuncSetAttribute(attn_kernel,
                         cudaFuncAttributeMaxDynamicSharedMemorySize, ATTN_SMEM);

    const int M = MROWS, D = DMODEL;

    // 1) round all GEMM inputs to tf32 (rna) for accuracy
    round_tf32_kernel<<<2048, 256>>>((const float4*)x,  (float4*)Xt,  M*D/4);
    round_tf32_kernel<<<2048, 256>>>((const float4*)Wq, (float4*)Wqt, D*D/4);
    round_tf32_kernel<<<2048, 256>>>((const float4*)Wk, (float4*)Wkt, D*D/4);
    round_tf32_kernel<<<2048, 256>>>((const float4*)Wv, (float4*)Wvt, D*D/4);
    round_tf32_kernel<<<2048, 256>>>((const float4*)Wo, (float4*)Wot, D*D/4);

    // 2) QKV projections: [4096,2048] x [2048,2048]; V output tf32-rounded
    dim3 gProj(D/128, M/128, 1);
    gemm_tf32_kernel<0><<<gProj, 256, SMEM_GEMM>>>(Xt, Wqt, Q,  D, D, D, D);
    gemm_tf32_kernel<0><<<gProj, 256, SMEM_GEMM>>>(Xt, Wkt, Kb, D, D, D, D);
    gemm_tf32_kernel<1><<<gProj, 256, SMEM_GEMM>>>(Xt, Wvt, V,  D, D, D, D);

    // 3) per-head RMSNorm on Q (folds in 1/sqrt(HDIM)) and K, tf32-rounded
    const float att_scale = 0.08838834764831845f;   // 1/sqrt(128)
    rmsnorm_kernel<<<M*NHEADS/8, 256>>>(Q,  qg, att_scale, M*NHEADS);
    rmsnorm_kernel<<<M*NHEADS/8, 256>>>(Kb, kg, 1.0f,      M*NHEADS);

    // 4) fused attention: AO = softmax_shifted(Q K^T) V, normalized in-kernel
    dim3 gAttn(SEQ/128, PAIRS, 1);
    attn_kernel<<<gAttn, 256, ATTN_SMEM>>>(Q, Kb, V, AO);

    // 5) output projection: out = AO x Wo
    gemm_tf32_kernel<0><<<gProj, 256, SMEM_GEMM>>>(AO, Wot, out, D, D, D, D);
}